// round 2
// baseline (speedup 1.0000x reference)
#include <cuda_runtime.h>

#define S 1024
#define DV 64
#define KF 32
#define NCOL 65536  // S*DV

typedef unsigned long long u64;

// ---------------- static scratch ----------------
__device__ float  d_bufA[(size_t)S*S*DV];
__device__ float  d_bufB[(size_t)S*S*DV];
__device__ float2 d_Gp[(size_t)4*KF*NCOL];   // partial fwd axis-0 DFT
__device__ float2 d_G [(size_t)KF*NCOL];     // [k1][s2*64+c]
__device__ float2 d_F [KF*KF*DV];            // [k1][k2][c]
__device__ float2 d_Rf[KF*KF*DV];            // [k1][k2][d]
__device__ float2 d_H [(size_t)S*KF*DV];     // [s1][k2][d]
__device__ float2 d_tw[S];                   // e^{+2pi i m/1024} = (cos, sin)

__device__ __forceinline__ u64 pack2(float x, float y){
    u64 r; asm("mov.b64 %0, {%1,%2};" : "=l"(r) : "f"(x), "f"(y)); return r;
}
__device__ __forceinline__ float2 unpack2(u64 v){
    float2 r; asm("mov.b64 {%0,%1}, %2;" : "=f"(r.x), "=f"(r.y) : "l"(v)); return r;
}
__device__ __forceinline__ u64 ffma2(u64 a, u64 b, u64 c){
    u64 d; asm("fma.rn.f32x2 %0, %1, %2, %3;" : "=l"(d) : "l"(a), "l"(b), "l"(c)); return d;
}
__device__ __forceinline__ float geluf(float x){
    return 0.5f * x * (1.0f + erff(x * 0.70710678118654752440f));
}

// ---------------- twiddle LUT ----------------
__global__ void k_tw(){
    int m = blockIdx.x*256 + threadIdx.x;
    double th = 6.283185307179586476925286766559 * ((double)m / 1024.0);
    d_tw[m] = make_float2((float)cos(th), (float)sin(th));
}

// ---------------- shallow: gelu(input @ Wsh + bsh) -> bufA ----------------
__global__ __launch_bounds__(256) void k_shallow(const float* __restrict__ in,
                                                 const float* __restrict__ Wsh,
                                                 const float* __restrict__ bsh){
    __shared__ float s_w[128], s_b[64], s_in[8];
    int t = threadIdx.x;
    size_t pb = (size_t)blockIdx.x * 4;
    if (t < 128) s_w[t] = Wsh[t];
    if (t < 64)  s_b[t] = bsh[t];
    if (t < 8)   s_in[t] = in[pb*2 + t];
    __syncthreads();
    int pl = t >> 6, c = t & 63;
    float v = s_in[pl*2]*s_w[c] + s_in[pl*2+1]*s_w[64+c] + s_b[c];
    d_bufA[(pb+pl)*64 + c] = geluf(v);
}

// ---------------- forward axis-0 truncated DFT (partials over 4 s1-chunks) ----
// Gp[q][k1][col] = sum_{s1 in chunk q} x[s1][col] * (cos - i sin)(2 pi k1 s1/1024)
__global__ __launch_bounds__(128) void k_f1(int flip){
    const float* __restrict__ X = flip ? d_bufB : d_bufA;
    __shared__ u64 s_tw[1024]; // [sl][k] = (cos, -sin)
    int t = threadIdx.x;
    int tx = t & 31, ty = t >> 5;
    int col0 = blockIdx.x*128 + tx*4;
    int q = blockIdx.y;
    int k0 = ty*8;
    u64 acc[32];
    #pragma unroll
    for (int i = 0; i < 32; i++) acc[i] = 0ull;

    for (int slab = 0; slab < 8; slab++){
        int s1b = q*256 + slab*32;
        __syncthreads();
        for (int e = t; e < 1024; e += 128){
            int sl = e >> 5, k = e & 31;
            float2 w = d_tw[(k*(s1b+sl)) & 1023];
            s_tw[e] = pack2(w.x, -w.y);
        }
        __syncthreads();
        const float* Xp = X + (size_t)s1b*NCOL + col0;
        #pragma unroll 4
        for (int sl = 0; sl < 32; sl++){
            float4 xv = *(const float4*)(Xp + (size_t)sl*NCOL);
            u64 x0 = pack2(xv.x,xv.x), x1 = pack2(xv.y,xv.y);
            u64 x2 = pack2(xv.z,xv.z), x3 = pack2(xv.w,xv.w);
            #pragma unroll
            for (int k = 0; k < 8; k++){
                u64 tw = s_tw[sl*32 + k0 + k];
                acc[k*4+0] = ffma2(x0, tw, acc[k*4+0]);
                acc[k*4+1] = ffma2(x1, tw, acc[k*4+1]);
                acc[k*4+2] = ffma2(x2, tw, acc[k*4+2]);
                acc[k*4+3] = ffma2(x3, tw, acc[k*4+3]);
            }
        }
    }
    #pragma unroll
    for (int k = 0; k < 8; k++)
        #pragma unroll
        for (int j = 0; j < 4; j++)
            d_Gp[((size_t)q*KF + k0 + k)*NCOL + col0 + j] = unpack2(acc[k*4+j]);
}

__global__ __launch_bounds__(256) void k_f1red(){
    size_t i = (size_t)blockIdx.x*256 + threadIdx.x;
    float2 a = d_Gp[i];
    #pragma unroll
    for (int q = 1; q < 4; q++){
        float2 b = d_Gp[(size_t)q*KF*NCOL + i];
        a.x += b.x; a.y += b.y;
    }
    d_G[i] = a;
}

// ---------------- forward axis-1: F[k1][k2][c] = sum_s2 G * e^{-2pi i k2 s2/1024} ----
__global__ __launch_bounds__(256) void k_f2(){
    int c  = threadIdx.x;
    int k2 = blockIdx.x*4 + threadIdx.y;
    int k1 = blockIdx.y;
    u64 acc = 0ull;
    const float2* Gp = d_G + (size_t)k1*NCOL + c;
    #pragma unroll 4
    for (int s2 = 0; s2 < S; s2++){
        float2 g = Gp[(size_t)s2*64];
        float2 w = d_tw[(k2*s2) & 1023];
        acc = ffma2(pack2(g.x,  g.y), pack2(w.x, w.x), acc);
        acc = ffma2(pack2(g.y, -g.x), pack2(w.y, w.y), acc);
    }
    d_F[((size_t)k1*KF + k2)*DV + c] = unpack2(acc);
}

// ---------------- per-mode mixing: Rf[k1,k2,d] = sum_c F[k1,k2,c]*(Rr+iRi)[k1,k2,c,d] ----
__global__ __launch_bounds__(256) void k_rmul(const float* __restrict__ Rr,
                                              const float* __restrict__ Ri){
    int d  = threadIdx.x;
    int k2 = blockIdx.x*4 + threadIdx.y;
    int k1 = blockIdx.y;
    size_t base = ((size_t)k1*KF + k2)*DV;
    u64 acc = 0ull;
    #pragma unroll 4
    for (int c = 0; c < DV; c++){
        float2 f = d_F[base + c];
        float rr = Rr[(base + c)*DV + d];
        float ri = Ri[(base + c)*DV + d];
        acc = ffma2(pack2( f.x, f.x), pack2(rr, ri), acc);
        acc = ffma2(pack2(-f.y, f.y), pack2(ri, rr), acc);
    }
    d_Rf[base + d] = unpack2(acc);
}

// ---------------- inverse axis-0: H[s1][k2][d] = alpha * sum_k1 Rf * e^{+2pi i k1 s1/1024} ----
__global__ __launch_bounds__(256) void k_i1(){
    int d  = threadIdx.x;
    int k2 = blockIdx.y*4 + threadIdx.y;
    int s1base = blockIdx.x*8;
    float2 rf[KF];
    #pragma unroll
    for (int k1 = 0; k1 < KF; k1++)
        rf[k1] = d_Rf[((size_t)k1*KF + k2)*DV + d];
    float alpha = (k2 == 0 ? 1.0f : 2.0f) * (1.0f/(1024.0f*1024.0f));
    for (int i = 0; i < 8; i++){
        int s1 = s1base + i;
        u64 acc = 0ull;
        #pragma unroll
        for (int k1 = 0; k1 < KF; k1++){
            float2 w = d_tw[(k1*s1) & 1023];
            acc = ffma2(pack2( rf[k1].x, rf[k1].x), pack2(w.x, w.y), acc);
            acc = ffma2(pack2(-rf[k1].y, rf[k1].y), pack2(w.y, w.x), acc);
        }
        float2 h = unpack2(acc);
        h.x *= alpha; h.y *= alpha;
        d_H[((size_t)s1*KF + k2)*DV + d] = h;
    }
}

// ---------------- inverse axis-1 + x@w + gelu, fused ----------------
// y[s1,s2,d] = gelu( sum_k2 (Hr cos - Hi sin) + sum_c x[s1,s2,c] w[c,d] )
__global__ __launch_bounds__(128) void k_i2(int flip, const float* __restrict__ w){
    const float* __restrict__ X = flip ? d_bufB : d_bufA;
    float* __restrict__ Y       = flip ? d_bufA : d_bufB;
    __shared__ float  s_hr[KF*DV];   // 8KB
    __shared__ float  s_hi[KF*DV];   // 8KB
    __shared__ float  s_w [DV*DV];   // 16KB
    __shared__ float  s_x [32*DV];   // 8KB
    __shared__ float2 s_cw[32*KF];   // 8KB  (cos, -sin)
    int t  = threadIdx.x;
    int tx = t & 15;          // d quad: d0 = tx*4
    int ty = t >> 4;          // s2 quad: s2l0 = ty*4
    int d0 = tx*4, s2l0 = ty*4;
    int s1 = blockIdx.y;

    for (int e = t; e < KF*DV; e += 128){
        float2 hv = d_H[(size_t)s1*KF*DV + e];
        s_hr[e] = hv.x; s_hi[e] = hv.y;
    }
    for (int e = t; e < DV*DV; e += 128) s_w[e] = w[e];

    for (int tile = blockIdx.x*8; tile < blockIdx.x*8 + 8; tile++){
        int s2base = tile*32;
        __syncthreads();
        for (int e = t; e < 512; e += 128)
            *(float4*)&s_x[e*4] = *(const float4*)&X[(size_t)s1*NCOL + (size_t)s2base*64 + e*4];
        for (int e = t; e < 32*KF; e += 128){
            int s2l = e >> 5, k2 = e & 31;
            float2 tw = d_tw[(k2*(s2base+s2l)) & 1023];
            s_cw[e] = make_float2(tw.x, -tw.y);
        }
        __syncthreads();

        u64 a[4][2];
        #pragma unroll
        for (int j = 0; j < 4; j++){ a[j][0] = 0ull; a[j][1] = 0ull; }

        #pragma unroll 4
        for (int k2 = 0; k2 < KF; k2++){
            ulonglong2 hr = *(const ulonglong2*)&s_hr[k2*DV + d0];
            ulonglong2 hi = *(const ulonglong2*)&s_hi[k2*DV + d0];
            #pragma unroll
            for (int j = 0; j < 4; j++){
                float2 cs = s_cw[(s2l0+j)*KF + k2];
                u64 cc = pack2(cs.x, cs.x), ns = pack2(cs.y, cs.y);
                a[j][0] = ffma2(hr.x, cc, a[j][0]);
                a[j][1] = ffma2(hr.y, cc, a[j][1]);
                a[j][0] = ffma2(hi.x, ns, a[j][0]);
                a[j][1] = ffma2(hi.y, ns, a[j][1]);
            }
        }
        #pragma unroll 8
        for (int c = 0; c < DV; c++){
            ulonglong2 wv = *(const ulonglong2*)&s_w[c*DV + d0];
            #pragma unroll
            for (int j = 0; j < 4; j++){
                float xv = s_x[(s2l0+j)*DV + c];
                u64 xx = pack2(xv, xv);
                a[j][0] = ffma2(wv.x, xx, a[j][0]);
                a[j][1] = ffma2(wv.y, xx, a[j][1]);
            }
        }
        #pragma unroll
        for (int j = 0; j < 4; j++){
            float2 v0 = unpack2(a[j][0]), v1 = unpack2(a[j][1]);
            float4 o;
            o.x = geluf(v0.x); o.y = geluf(v0.y);
            o.z = geluf(v1.x); o.w = geluf(v1.y);
            *(float4*)&Y[(size_t)s1*NCOL + (size_t)(s2base+s2l0+j)*64 + d0] = o;
        }
    }
}

// ---------------- projection: out[p] = sum_c vt[p,c]*Wp[c] + bp[0] ----------------
__global__ __launch_bounds__(256) void k_proj(const float* __restrict__ Wp,
                                              const float* __restrict__ bp,
                                              float* __restrict__ out){
    int t = threadIdx.x, lane = t & 31, wq = t >> 5;
    size_t p = (size_t)blockIdx.x*8 + wq;
    const float* vp = d_bufA + p*64;
    float s = vp[lane]*Wp[lane] + vp[lane+32]*Wp[lane+32];
    #pragma unroll
    for (int off = 16; off > 0; off >>= 1)
        s += __shfl_xor_sync(0xffffffffu, s, off);
    if (lane == 0) out[p] = s + bp[0];
}

extern "C" void kernel_launch(void* const* d_in, const int* in_sizes, int n_in,
                              void* d_out, int out_size){
    const float* in  = (const float*)d_in[0];
    const float* Wsh = (const float*)d_in[1];
    const float* bsh = (const float*)d_in[2];
    const float* Rr[4] = {(const float*)d_in[3], (const float*)d_in[6],
                          (const float*)d_in[9], (const float*)d_in[12]};
    const float* Ri[4] = {(const float*)d_in[4], (const float*)d_in[7],
                          (const float*)d_in[10], (const float*)d_in[13]};
    const float* ww[4] = {(const float*)d_in[5], (const float*)d_in[8],
                          (const float*)d_in[11], (const float*)d_in[14]};
    const float* Wp = (const float*)d_in[15];
    const float* bp = (const float*)d_in[16];
    float* out = (float*)d_out;

    k_tw<<<4,256>>>();
    k_shallow<<<S*S/4, 256>>>(in, Wsh, bsh);
    for (int l = 0; l < 4; l++){
        int flip = l & 1;
        k_f1<<<dim3(512,4), 128>>>(flip);
        k_f1red<<<KF*NCOL/256, 256>>>();
        k_f2<<<dim3(8,32), dim3(64,4)>>>();
        k_rmul<<<dim3(8,32), dim3(64,4)>>>(Rr[l], Ri[l]);
        k_i1<<<dim3(128,8), dim3(64,4)>>>();
        k_i2<<<dim3(4,1024), 128>>>(flip, ww[l]);
    }
    k_proj<<<S*S/8, 256>>>(Wp, bp, out);
}